// round 2
// baseline (speedup 1.0000x reference)
#include <cuda_runtime.h>
#include <stdint.h>

#define NUM_CLASSES 1000
#define BUF 512
#define DIM 256
#define D4  (DIM / 4)      // 64 float4 per row
#define NQ  65536
#define KK  16

// Scratch (allocation-free device globals)
__device__ int g_topi[NUM_CLASSES * KK];  // per-class top-16 slot indices
__device__ int g_lab64;                   // 1 if labels are int64, 0 if int32

// ---------------------------------------------------------------------------
// Kernel 0: detect label dtype. int64 labels (<1000) have all-zero high words;
// int32 labels in [0,1000) make "all 32 odd words zero" astronomically unlikely.
// ---------------------------------------------------------------------------
__global__ void detect_kernel(const unsigned int* __restrict__ labels_raw)
{
    int is64 = 1;
    for (int i = 1; i < 64; i += 2)
        if (labels_raw[i] != 0u) is64 = 0;
    g_lab64 = is64;
}

// ---------------------------------------------------------------------------
// Kernel 1: stable top-16 per class via rank counting.
// rank(i) = #{ j : a_j > a_i  OR (a_j == a_i AND j < i) }
// Matches jax.lax.top_k: descending values, ties broken by lower index.
// Ranks are unique even under exact ties -> conflict-free writes.
// ---------------------------------------------------------------------------
__global__ void __launch_bounds__(BUF) topk_kernel(const float* __restrict__ areas)
{
    __shared__ float s[BUF];
    const int c = blockIdx.x;
    const int i = threadIdx.x;

    const float a = areas[c * BUF + i];
    s[i] = a;
    __syncthreads();

    int rank = 0;
#pragma unroll 16
    for (int j = 0; j < BUF; ++j) {
        const float aj = s[j];
        rank += (aj > a) | ((aj == a) & (j < i));
    }

    if (rank < KK) {
        g_topi[c * KK + rank] = i;
    }
}

// ---------------------------------------------------------------------------
// Kernel 2: gather. One block per query n.
// Block writes 16 rows x 256 floats = 1024 float4. 256 threads, 4 float4 each.
// Reads hit L2 (16 MB distinct working set); writes use streaming hint (__stcs)
// to avoid evicting the hot buffer rows from L2.
// ---------------------------------------------------------------------------
__global__ void __launch_bounds__(256) gather_kernel(
    const float4* __restrict__ buffer,   // [C, B, D4]
    const void*   __restrict__ labels,   // [NQ] int32 or int64
    float4*       __restrict__ out)      // [NQ, K, D4]
{
    const int n = blockIdx.x;
    const int c = g_lab64 ? (int)((const long long*)labels)[n]
                          : ((const int*)labels)[n];

    __shared__ int sidx[KK];
    if (threadIdx.x < KK) {
        sidx[threadIdx.x] = g_topi[c * KK + threadIdx.x];
    }
    __syncthreads();

    const float4* src_base = buffer + (size_t)c * (BUF * D4);
    float4* dst_base = out + (size_t)n * (KK * D4);

#pragma unroll
    for (int r = 0; r < 4; ++r) {
        const int i  = threadIdx.x + r * 256;   // 0..1023
        const int j  = i >> 6;                  // token index 0..15
        const int d4 = i & (D4 - 1);            // 0..63
        const float4 v = __ldg(src_base + sidx[j] * D4 + d4);
        __stcs(dst_base + i, v);                // out row-major: (j, d4) == i
    }
}

extern "C" void kernel_launch(void* const* d_in, const int* in_sizes, int n_in,
                              void* d_out, int out_size)
{
    // Identify inputs by unique element counts (robust to metadata ordering).
    const void* buffer = 0;
    const void* areas  = 0;
    const void* labels = 0;
    for (int i = 0; i < n_in; ++i) {
        if (in_sizes[i] == NUM_CLASSES * BUF * DIM) buffer = d_in[i];
        else if (in_sizes[i] == NUM_CLASSES * BUF)  areas  = d_in[i];
        else if (in_sizes[i] == NQ)                 labels = d_in[i];
        // sizes 1000 (pointer) and 1 (k) are validation-only, unused
    }

    detect_kernel<<<1, 1>>>((const unsigned int*)labels);
    topk_kernel<<<NUM_CLASSES, BUF>>>((const float*)areas);
    gather_kernel<<<NQ, 256>>>((const float4*)buffer, labels, (float4*)d_out);
}

// round 3
// speedup vs baseline: 1.0026x; 1.0026x over previous
#include <cuda_runtime.h>
#include <stdint.h>

#define NUM_CLASSES 1000
#define BUF 512
#define DIM 256
#define D4  (DIM / 4)      // 64 float4 per row
#define NQ  65536
#define KK  16

// Scratch (allocation-free device globals)
__device__ int g_topi[NUM_CLASSES * KK];  // per-class top-16 slot indices
__device__ int g_lab64;                   // 1 if labels are int64, 0 if int32

// ---------------------------------------------------------------------------
// Kernel 0: detect label dtype. int64 labels (<1000) have all-zero high words;
// int32 labels in [0,1000) make "all 32 odd words zero" astronomically unlikely.
// ---------------------------------------------------------------------------
__global__ void detect_kernel(const unsigned int* __restrict__ labels_raw)
{
    int is64 = 1;
    for (int i = 1; i < 64; i += 2)
        if (labels_raw[i] != 0u) is64 = 0;
    g_lab64 = is64;
}

// ---------------------------------------------------------------------------
// Kernel 1: stable top-16 per class via rank counting.
// rank(i) = #{ j : a_j > a_i  OR (a_j == a_i AND j < i) }
// Matches jax.lax.top_k: descending values, ties broken by lower index.
// Ranks are unique even under exact ties -> conflict-free writes.
// ---------------------------------------------------------------------------
__global__ void __launch_bounds__(BUF) topk_kernel(const float* __restrict__ areas)
{
    __shared__ float s[BUF];
    const int c = blockIdx.x;
    const int i = threadIdx.x;

    const float a = areas[c * BUF + i];
    s[i] = a;
    __syncthreads();

    int rank = 0;
#pragma unroll 16
    for (int j = 0; j < BUF; ++j) {
        const float aj = s[j];
        rank += (aj > a) | ((aj == a) & (j < i));
    }

    if (rank < KK) {
        g_topi[c * KK + rank] = i;
    }
}

// ---------------------------------------------------------------------------
// Kernel 2: gather. One block per query n.
// Block writes 16 rows x 256 floats = 1024 float4. 256 threads, 4 float4 each.
// Reads hit L2 (16 MB distinct working set); writes use streaming hint (__stcs)
// to avoid evicting the hot buffer rows from L2.
// ---------------------------------------------------------------------------
__global__ void __launch_bounds__(256) gather_kernel(
    const float4* __restrict__ buffer,   // [C, B, D4]
    const void*   __restrict__ labels,   // [NQ] int32 or int64
    float4*       __restrict__ out)      // [NQ, K, D4]
{
    const int n = blockIdx.x;
    const int c = g_lab64 ? (int)((const long long*)labels)[n]
                          : ((const int*)labels)[n];

    __shared__ int sidx[KK];
    if (threadIdx.x < KK) {
        sidx[threadIdx.x] = g_topi[c * KK + threadIdx.x];
    }
    __syncthreads();

    const float4* src_base = buffer + (size_t)c * (BUF * D4);
    float4* dst_base = out + (size_t)n * (KK * D4);

#pragma unroll
    for (int r = 0; r < 4; ++r) {
        const int i  = threadIdx.x + r * 256;   // 0..1023
        const int j  = i >> 6;                  // token index 0..15
        const int d4 = i & (D4 - 1);            // 0..63
        const float4 v = __ldg(src_base + sidx[j] * D4 + d4);
        __stcs(dst_base + i, v);                // out row-major: (j, d4) == i
    }
}

extern "C" void kernel_launch(void* const* d_in, const int* in_sizes, int n_in,
                              void* d_out, int out_size)
{
    // Identify inputs by unique element counts (robust to metadata ordering).
    const void* buffer = 0;
    const void* areas  = 0;
    const void* labels = 0;
    for (int i = 0; i < n_in; ++i) {
        if (in_sizes[i] == NUM_CLASSES * BUF * DIM) buffer = d_in[i];
        else if (in_sizes[i] == NUM_CLASSES * BUF)  areas  = d_in[i];
        else if (in_sizes[i] == NQ)                 labels = d_in[i];
        // sizes 1000 (pointer) and 1 (k) are validation-only, unused
    }

    detect_kernel<<<1, 1>>>((const unsigned int*)labels);
    topk_kernel<<<NUM_CLASSES, BUF>>>((const float*)areas);
    gather_kernel<<<NQ, 256>>>((const float4*)buffer, labels, (float4*)d_out);
}